// round 6
// baseline (speedup 1.0000x reference)
#include <cuda_runtime.h>

// ----------------------------------------------------------------------------
// FBP pipeline (2 kernels):
//   K1: filter  — circular conv of the 16 BASE frames with the exact
//       closed-form ramp kernel (h[0]=1/4, h odd = -1/(16384 sin^2(pi n/128)),
//       h even = 0), scaled by pi/128.  (filter ∘ lerp = lerp ∘ filter)
//   K2: backproject — 2 slices per block, 1024 threads (32 warps/SM, 64 regs):
//       lerp 16 frames -> 128 angle rows in smem (guard-padded, 192 KB);
//       lane = consecutive y -> conflict-free LDS at every angle; floor folded
//       directly into the LDS byte address (fp32 magic, mod-2^32 exact).
// ----------------------------------------------------------------------------

#define MPIF 3.14159265358979323846f

__device__ float g_Fbase[16 * 1024 * 128];       // filtered base frames, 8 MB

// --------------------------- K1: filter -------------------------------------
__global__ __launch_bounds__(256) void k_filter(const float* __restrict__ feat) {
    __shared__ float hk[256];                    // hker duplicated: hk[i]=h[i&127]
    int tid = threadIdx.x;
    {
        int n = tid & 127;
        float h;
        if (n == 0) h = 0.25f;
        else if (n & 1) {
            float sv = sinpif((float)n * (1.0f / 128.0f));
            h = -1.0f / (16384.0f * sv * sv);
        } else h = 0.0f;
        hk[tid] = h * (MPIF / 128.0f);           // fold pi/A scale into filter
    }
    __syncthreads();

    int lane = tid & 31;
    int wid  = tid >> 5;
    int r = blockIdx.x * 8 + wid;                // row 0..16383
    const float* row = feat + (size_t)r * 128;

    float rv[4];
    rv[0] = row[lane];      rv[1] = row[lane + 32];
    rv[2] = row[lane + 64]; rv[3] = row[lane + 96];
    float a0 = 0.f, a1 = 0.f, a2 = 0.f, a3 = 0.f;

#pragma unroll
    for (int kb = 0; kb < 4; kb++) {
        float rsel = rv[kb];
#pragma unroll
        for (int kk = 0; kk < 32; kk++) {
            float x = __shfl_sync(0xffffffffu, rsel, kk);
            int base = lane + 128 - (kb * 32 + kk);   // in [1,255]
            a0 += x * hk[base];
            a1 += x * hk[base + 32];
            a2 += x * hk[base + 64];
            a3 += x * hk[base + 96];
        }
    }
    float* o = g_Fbase + (size_t)r * 128;
    o[lane] = a0; o[lane + 32] = a1; o[lane + 64] = a2; o[lane + 96] = a3;
}

// ------------------------ K2: backprojection --------------------------------
extern __shared__ float s_FA[];

static constexpr int FA_STRIDE = 192;              // padded row (floats)
static constexpr int FA_SLICE  = 128 * FA_STRIDE;  // floats per slice (24576)
static constexpr int FA_SLICE_B = FA_SLICE * 4;    // 98304 bytes

__global__ __launch_bounds__(1024, 1) void k_bp(float* __restrict__ out) {
    __shared__ float sc[128], ss[128];

    int tid = threadIdx.x;
    int s0  = blockIdx.x * 2;                    // slices s0, s0+1

    if (tid < 128) {
        float t = (float)tid * (1.0f / 128.0f);
        sc[tid] = cospif(t);
        ss[tid] = sinpif(t);
    }

    // zero guard bands: 2 slices x 128 angles x (32 left + 32 right)
    for (int g = tid; g < 2 * 8192; g += 1024) {
        int sl = g >> 13;
        int gg = g & 8191;
        int a = gg >> 6;
        int q = gg & 63;
        int col = (q < 32) ? q : (128 + q);      // [0,32) and [160,192)
        s_FA[sl * FA_SLICE + a * FA_STRIDE + col] = 0.f;
    }

    // interior: lerp 16 filtered base frames -> 128 angle rows, both slices
    for (int e = tid; e < 2 * 16384; e += 1024) {
        int sl = e >> 14;
        int ee = e & 16383;
        int a = ee >> 7, w = ee & 127;
        int t0 = a >> 3;
        float v = (float)(a & 7) * 0.125f;
        int s = s0 + sl;
        float f0 = g_Fbase[(size_t)(t0 * 1024 + s) * 128 + w];
        float f1 = g_Fbase[(size_t)(((t0 + 1) & 15) * 1024 + s) * 128 + w];
        s_FA[sl * FA_SLICE + a * FA_STRIDE + 32 + w] = fmaf(v, f1 - f0, f0);
    }
    __syncthreads();

    // 32 warps: lane = y (consecutive), warp -> (x phase, i half)
    int w5 = tid >> 5;                           // 0..31
    int l  = tid & 31;
    int xg = (w5 & 15) + 16 * (w5 >> 4);         // x = xg + 32*i, i<4
    float xb = (float)xg - 63.5f;

    unsigned sbase = (unsigned)__cvta_generic_to_shared(s_FA);

    float acc0[16], acc1[16];                    // [i*4+j], per slice
#pragma unroll
    for (int i = 0; i < 16; i++) { acc0[i] = 0.f; acc1[i] = 0.f; }

    for (int a = 0; a < 128; a++) {
        float c  = sc[a];
        float sn = ss[a];
        float lsn = fmaf((float)l, sn, 95.5f);   // +63.5 center +32 guard
        // magic-adjusted row base: addr = rb + 4*float_as_int(u + 2^23-0.5)
        unsigned rb = sbase + (unsigned)(a * (FA_STRIDE * 4)) - 0x2C000000u;
#pragma unroll
        for (int i = 0; i < 4; i++) {
            float xc = fmaf(xb + (float)(32 * i), c, lsn);
#pragma unroll
            for (int j = 0; j < 4; j++) {
                float u  = fmaf((float)(32 * j) - 63.5f, sn, xc);
                float t  = u + 8388607.5f;             // 2^23-0.5: RN->floor
                float fl = t - 8388608.0f;             // floor(u), exact
                float fr = u - fl;                     // frac, exact
                float om = 1.0f - fr;
                unsigned addr = rb + (unsigned)__float_as_int(t) * 4u;
                float g0a, g1a, g0b, g1b;
                asm("ld.shared.f32 %0, [%1];"       : "=f"(g0a) : "r"(addr));
                asm("ld.shared.f32 %0, [%1+4];"     : "=f"(g1a) : "r"(addr));
                asm("ld.shared.f32 %0, [%1+98304];" : "=f"(g0b) : "r"(addr));
                asm("ld.shared.f32 %0, [%1+98308];" : "=f"(g1b) : "r"(addr));
                int k = i * 4 + j;
                acc0[k] = fmaf(g0a, om, fmaf(g1a, fr, acc0[k]));
                acc1[k] = fmaf(g0b, om, fmaf(g1b, fr, acc1[k]));
            }
        }
    }

    // out[s, x, y]: x = xg + 32*i, y = 32*j + l; lane-consecutive -> coalesced
    float* ob = out + (size_t)s0 * 16384 + l;
#pragma unroll
    for (int i = 0; i < 4; i++) {
#pragma unroll
        for (int j = 0; j < 4; j++) {
            int k = i * 4 + j;
            int off = (xg + 32 * i) * 128 + 32 * j;
            ob[off] = acc0[k];
            ob[16384 + off] = acc1[k];
        }
    }
}

// ----------------------------------------------------------------------------
extern "C" void kernel_launch(void* const* d_in, const int* in_sizes, int n_in,
                              void* d_out, int out_size) {
    (void)in_sizes; (void)n_in; (void)out_size;
    const float* feat = (const float*)d_in[0];
    float* out = (float*)d_out;

    int smem_bytes = 2 * FA_SLICE * (int)sizeof(float);   // 196608
    cudaFuncSetAttribute(k_bp, cudaFuncAttributeMaxDynamicSharedMemorySize,
                         smem_bytes);

    k_filter<<<2048, 256>>>(feat);
    k_bp<<<512, 1024, smem_bytes>>>(out);
}

// round 7
// speedup vs baseline: 2.5044x; 2.5044x over previous
#include <cuda_runtime.h>
#include <cuda_fp16.h>

// ----------------------------------------------------------------------------
// FBP pipeline (2 kernels):
//   K1: filter — circular conv of the 16 BASE frames with the exact
//       closed-form ramp kernel (scaled by pi/128). (filter ∘ lerp = lerp ∘ filter)
//   K2: backproject — 4 slices per block, fp16x2 slice-packed FA in smem:
//       one 32-bit LDS = one tap for 2 slices; index math shared by 4 slices.
//       1024 threads, 16 fp32 accumulators/thread (no spill), lane = consecutive
//       y -> conflict-free LDS at every angle; floor folded into LDS address.
// ----------------------------------------------------------------------------

#define MPIF 3.14159265358979323846f

__device__ float g_Fbase[16 * 1024 * 128];       // filtered base frames, 8 MB

// --------------------------- K1: filter -------------------------------------
__global__ __launch_bounds__(256) void k_filter(const float* __restrict__ feat) {
    __shared__ float hk[256];                    // hker duplicated: hk[i]=h[i&127]
    int tid = threadIdx.x;
    {
        int n = tid & 127;
        float h;
        if (n == 0) h = 0.25f;
        else if (n & 1) {
            float sv = sinpif((float)n * (1.0f / 128.0f));
            h = -1.0f / (16384.0f * sv * sv);
        } else h = 0.0f;
        hk[tid] = h * (MPIF / 128.0f);           // fold pi/A scale into filter
    }
    __syncthreads();

    int lane = tid & 31;
    int wid  = tid >> 5;
    int r = blockIdx.x * 8 + wid;                // row 0..16383
    const float* row = feat + (size_t)r * 128;

    float rv[4];
    rv[0] = row[lane];      rv[1] = row[lane + 32];
    rv[2] = row[lane + 64]; rv[3] = row[lane + 96];
    float a0 = 0.f, a1 = 0.f, a2 = 0.f, a3 = 0.f;

#pragma unroll
    for (int kb = 0; kb < 4; kb++) {
        float rsel = rv[kb];
#pragma unroll
        for (int kk = 0; kk < 32; kk++) {
            float x = __shfl_sync(0xffffffffu, rsel, kk);
            int base = lane + 128 - (kb * 32 + kk);   // in [1,255]
            a0 += x * hk[base];
            a1 += x * hk[base + 32];
            a2 += x * hk[base + 64];
            a3 += x * hk[base + 96];
        }
    }
    float* o = g_Fbase + (size_t)r * 128;
    o[lane] = a0; o[lane + 32] = a1; o[lane + 64] = a2; o[lane + 96] = a3;
}

// ------------------------ K2: backprojection --------------------------------
// grid = 1024: block b -> quad = b>>2 (slices 4q..4q+3), part = b&3 (x band).
// smem: two packed arrays (pair0 = slices 0,1; pair1 = slices 2,3), each
// 128 rows x 192 half2 cols (32-col zero guards each side) = 98304 B.
static constexpr int PFA_SLOTS = 128 * 192;          // half2 slots per pair
extern __shared__ __align__(16) unsigned s_pfa[];    // 2 * PFA_SLOTS

__global__ __launch_bounds__(1024, 1) void k_bp(float* __restrict__ out) {
    __shared__ float sc[128], ss[128];

    int tid = threadIdx.x;
    int quad = blockIdx.x >> 2;
    int part = blockIdx.x & 3;
    int sl0  = quad * 4;                         // first of 4 slices

    if (tid < 128) {
        float t = (float)tid * (1.0f / 128.0f);
        sc[tid] = cospif(t);
        ss[tid] = sinpif(t);
    }

    // zero guard bands: 2 pairs x 128 rows x (32 left + 32 right)
    for (int g = tid; g < 16384; g += 1024) {
        int arr = g >> 13;
        int gg  = g & 8191;
        int a   = gg >> 6;
        int q   = gg & 63;
        int col = (q < 32) ? q : (128 + q);      // [0,32) and [160,192)
        s_pfa[arr * PFA_SLOTS + a * 192 + col] = 0u;
    }

    // interior fill: thread -> (w, pair p, angle quarter r).
    // Load 5 frames x 2 slices into regs, emit 32 packed angle rows.
    {
        int w = tid & 127;
        int z = tid >> 7;                        // 0..7
        int p = z & 1;                           // slice pair
        int r = z >> 1;                          // angle quarter
        int s0 = sl0 + 2 * p;
        float f0v[5], f1v[5];
#pragma unroll
        for (int k = 0; k < 5; k++) {
            int t = (4 * r + k) & 15;
            f0v[k] = g_Fbase[((size_t)t * 1024 + s0) * 128 + w];
            f1v[k] = g_Fbase[((size_t)t * 1024 + s0 + 1) * 128 + w];
        }
        unsigned* pf = s_pfa + p * PFA_SLOTS;
#pragma unroll
        for (int aa = 0; aa < 32; aa++) {
            int a = r * 32 + aa;
            int k = aa >> 3;
            float v = (float)(a & 7) * 0.125f;
            float v0 = fmaf(v, f0v[k + 1] - f0v[k], f0v[k]);
            float v1 = fmaf(v, f1v[k + 1] - f1v[k], f1v[k]);
            __half2 h = __floats2half2_rn(v0, v1);
            pf[a * 192 + 32 + w] = *reinterpret_cast<unsigned*>(&h);
        }
    }
    __syncthreads();

    // main loop: warp -> x = part*32 + warpid, lane = y (consecutive),
    // 4 y-groups x 4 slices = 16 fp32 accumulators.
    int w5 = tid >> 5;
    int l  = tid & 31;
    int x  = part * 32 + w5;
    float xa = (float)x - 63.5f;

    unsigned sb = (unsigned)__cvta_generic_to_shared(s_pfa);

    float acc[4][4];                             // [j][slice]
#pragma unroll
    for (int j = 0; j < 4; j++)
#pragma unroll
        for (int s = 0; s < 4; s++) acc[j][s] = 0.f;

    for (int a = 0; a < 128; a++) {
        float c  = sc[a];
        float sn = ss[a];
        float lsn = fmaf((float)l, sn, 95.5f);   // +63.5 center +32 guard
        float xc  = fmaf(xa, c, lsn);
        // magic-adjusted row base: addr = rb + 4*float_as_int(u + 2^23-0.5)
        unsigned rb = sb + (unsigned)(a * 768) - 0x2C000000u;
#pragma unroll
        for (int j = 0; j < 4; j++) {
            float u  = fmaf((float)(32 * j) - 63.5f, sn, xc);
            float t  = u + 8388607.5f;           // 2^23-0.5: RN -> floor
            float fl = t - 8388608.0f;           // floor(u), exact
            float fr = u - fl;                   // frac, exact
            __half2 fr2 = __float2half2_rn(fr);
            unsigned addr = rb + (unsigned)__float_as_int(t) * 4u;
            unsigned r0a, r1a, r0b, r1b;
            asm("ld.shared.b32 %0, [%1];"        : "=r"(r0a) : "r"(addr));
            asm("ld.shared.b32 %0, [%1+4];"      : "=r"(r1a) : "r"(addr));
            asm("ld.shared.b32 %0, [%1+98304];"  : "=r"(r0b) : "r"(addr));
            asm("ld.shared.b32 %0, [%1+98308];"  : "=r"(r1b) : "r"(addr));
            __half2 g0a = *reinterpret_cast<__half2*>(&r0a);
            __half2 g1a = *reinterpret_cast<__half2*>(&r1a);
            __half2 g0b = *reinterpret_cast<__half2*>(&r0b);
            __half2 g1b = *reinterpret_cast<__half2*>(&r1b);
            __half2 pa = __hfma2(fr2, __hsub2(g1a, g0a), g0a);
            __half2 pb = __hfma2(fr2, __hsub2(g1b, g0b), g0b);
            float2 fa2 = __half22float2(pa);
            float2 fb2 = __half22float2(pb);
            acc[j][0] += fa2.x;  acc[j][1] += fa2.y;
            acc[j][2] += fb2.x;  acc[j][3] += fb2.y;
        }
    }

    // out[s, x, y]: y = 32*j + l, lane-consecutive -> coalesced 128B stores
    float* ob = out + (size_t)sl0 * 16384 + x * 128 + l;
#pragma unroll
    for (int s = 0; s < 4; s++)
#pragma unroll
        for (int j = 0; j < 4; j++)
            ob[s * 16384 + 32 * j] = acc[j][s];
}

// ----------------------------------------------------------------------------
extern "C" void kernel_launch(void* const* d_in, const int* in_sizes, int n_in,
                              void* d_out, int out_size) {
    (void)in_sizes; (void)n_in; (void)out_size;
    const float* feat = (const float*)d_in[0];
    float* out = (float*)d_out;

    int smem_bytes = 2 * PFA_SLOTS * (int)sizeof(unsigned);   // 196608
    cudaFuncSetAttribute(k_bp, cudaFuncAttributeMaxDynamicSharedMemorySize,
                         smem_bytes);

    k_filter<<<2048, 256>>>(feat);
    k_bp<<<1024, 1024, smem_bytes>>>(out);
}

// round 9
// speedup vs baseline: 3.1241x; 1.2474x over previous
#include <cuda_runtime.h>
#include <cuda_fp16.h>

#define MPIF 3.14159265358979323846f

// ----------------------------------------------------------------------------
// FBP pipeline (2 kernels, SIMT — tcgen05 unavailable: harness lowers via
// compute_103 which rejects arch-specific PTX):
//   K1: filter — circular conv of the 16 BASE frames with the exact
//       closed-form ramp kernel (scaled by pi/128). (filter ∘ lerp = lerp ∘ filter)
//   K2: backproject — 4 slices per block packed as ONE 64-bit smem slot
//       (4 x fp16): one LDS.64 = one tap for all 4 slices. Index math shared
//       by 4 slices; fp16 run-accumulation (4 angles) flushed to fp32.
//       Lane = consecutive y -> conflict-free LDS; floor folded into address.
// ----------------------------------------------------------------------------

__device__ float g_Fbase[16 * 1024 * 128];       // filtered base frames, 8 MB

// --------------------------- K1: filter -------------------------------------
__global__ __launch_bounds__(256) void k_filter(const float* __restrict__ feat) {
    __shared__ float hk[256];                    // hker duplicated: hk[i]=h[i&127]
    int tid = threadIdx.x;
    {
        int n = tid & 127;
        float h;
        if (n == 0) h = 0.25f;
        else if (n & 1) {
            float sv = sinpif((float)n * (1.0f / 128.0f));
            h = -1.0f / (16384.0f * sv * sv);
        } else h = 0.0f;
        hk[tid] = h * (MPIF / 128.0f);           // fold pi/A scale into filter
    }
    __syncthreads();

    int lane = tid & 31;
    int wid  = tid >> 5;
    int r = blockIdx.x * 8 + wid;                // row 0..16383 = t*1024 + s
    const float* row = feat + (size_t)r * 128;

    float rv[4];
    rv[0] = row[lane];      rv[1] = row[lane + 32];
    rv[2] = row[lane + 64]; rv[3] = row[lane + 96];
    float a0 = 0.f, a1 = 0.f, a2 = 0.f, a3 = 0.f;

#pragma unroll
    for (int kb = 0; kb < 4; kb++) {
        float rsel = rv[kb];
#pragma unroll
        for (int kk = 0; kk < 32; kk++) {
            float x = __shfl_sync(0xffffffffu, rsel, kk);
            int base = lane + 128 - (kb * 32 + kk);   // in [1,255]
            a0 += x * hk[base];
            a1 += x * hk[base + 32];
            a2 += x * hk[base + 64];
            a3 += x * hk[base + 96];
        }
    }
    float* o = g_Fbase + (size_t)r * 128;
    o[lane] = a0; o[lane + 32] = a1; o[lane + 64] = a2; o[lane + 96] = a3;
}

// ------------------------ K2: backprojection --------------------------------
// grid = 1024: block b -> quad = b>>2 (slices 4q..4q+3), part = b&3 (x band).
// smem: 128 angle rows x 192 slots, slot = 8B = 4 x fp16 (slices 0..3),
// 32-slot zero guards each side. 196608 B total.
static constexpr int QROW = 192;                     // slots per angle row
extern __shared__ __align__(16) unsigned long long s_q[];   // 128*192 slots

__global__ __launch_bounds__(1024, 1) void k_bp(float* __restrict__ out) {
    __shared__ float2 scs[128];                  // (cos, sin)

    int tid  = threadIdx.x;
    int quad = blockIdx.x >> 2;
    int part = blockIdx.x & 3;
    int sl0  = quad * 4;                         // first of 4 slices

    if (tid < 128) {
        float t = (float)tid * (1.0f / 128.0f);
        scs[tid] = make_float2(cospif(t), sinpif(t));
    }

    // zero guard slots: 128 rows x (32 left + 32 right)
    for (int g = tid; g < 8192; g += 1024) {
        int a = g >> 6;
        int q = g & 63;
        int col = (q < 32) ? q : (128 + q);      // [0,32) and [160,192)
        s_q[a * QROW + col] = 0ull;
    }

    // interior fill: thread -> (w, angle eighth z). 3 frames x 4 slices in regs,
    // emit 16 packed angle rows of one detector column.
    {
        int w = tid & 127;
        int z = tid >> 7;                        // 0..7 -> angles [16z,16z+16)
        float f[3][4], d[2][4];
#pragma unroll
        for (int k = 0; k < 3; k++) {
            int t = (2 * z + k) & 15;
#pragma unroll
            for (int s = 0; s < 4; s++)
                f[k][s] = g_Fbase[((size_t)t * 1024 + sl0 + s) * 128 + w];
        }
#pragma unroll
        for (int k = 0; k < 2; k++)
#pragma unroll
            for (int s = 0; s < 4; s++) d[k][s] = f[k + 1][s] - f[k][s];

#pragma unroll
        for (int aa = 0; aa < 16; aa++) {
            int a = z * 16 + aa;
            int k = aa >> 3;
            float v = (float)(aa & 7) * 0.125f;
            float v0 = fmaf(v, d[k][0], f[k][0]);
            float v1 = fmaf(v, d[k][1], f[k][1]);
            float v2 = fmaf(v, d[k][2], f[k][2]);
            float v3 = fmaf(v, d[k][3], f[k][3]);
            __half2 lo = __floats2half2_rn(v0, v1);
            __half2 hi = __floats2half2_rn(v2, v3);
            unsigned long long pk =
                (unsigned long long)(*reinterpret_cast<unsigned*>(&lo)) |
                ((unsigned long long)(*reinterpret_cast<unsigned*>(&hi)) << 32);
            s_q[a * QROW + 32 + w] = pk;
        }
    }
    __syncthreads();

    // main loop: warp -> x = part*32 + warpid, lane = y (consecutive).
    int w5 = tid >> 5;
    int l  = tid & 31;
    int x  = part * 32 + w5;
    float xa = (float)x - 63.5f;
    float la = (float)l;

    unsigned sb = (unsigned)__cvta_generic_to_shared(s_q);

    float acc[4][4];                             // [j][slice] fp32
#pragma unroll
    for (int j = 0; j < 4; j++)
#pragma unroll
        for (int s = 0; s < 4; s++) acc[j][s] = 0.f;

    const __half2 hz = __float2half2_rn(0.f);

    for (int run = 0; run < 32; run++) {
        __half2 hA[4], hB[4];                    // run accumulators: (s0,s1),(s2,s3)
#pragma unroll
        for (int j = 0; j < 4; j++) { hA[j] = hz; hB[j] = hz; }

#pragma unroll
        for (int aa = 0; aa < 4; aa++) {
            int a = run * 4 + aa;
            float2 cs = scs[a];
            float xc = fmaf(xa, cs.x, fmaf(la, cs.y, 95.5f)); // center+guard
            // magic row base: addr = rb + 8*float_as_int(u + 2^23-0.5)
            unsigned rb = sb + (unsigned)(a * (QROW * 8)) - 0x58000000u;
#pragma unroll
            for (int j = 0; j < 4; j++) {
                float u  = fmaf((float)(32 * j) - 63.5f, cs.y, xc);
                float t  = u + 8388607.5f;       // 2^23-0.5: RN -> floor
                float fl = t - 8388608.0f;       // floor(u), exact
                float fr = u - fl;               // frac, exact
                __half2 fr2 = __float2half2_rn(fr);
                unsigned addr = rb + (unsigned)__float_as_int(t) * 8u;
                unsigned g0lo, g0hi, g1lo, g1hi;
                asm("ld.shared.v2.b32 {%0,%1}, [%2];"
                    : "=r"(g0lo), "=r"(g0hi) : "r"(addr));
                asm("ld.shared.v2.b32 {%0,%1}, [%2+8];"
                    : "=r"(g1lo), "=r"(g1hi) : "r"(addr));
                __half2 a0 = *reinterpret_cast<__half2*>(&g0lo);
                __half2 b0 = *reinterpret_cast<__half2*>(&g0hi);
                __half2 a1 = *reinterpret_cast<__half2*>(&g1lo);
                __half2 b1 = *reinterpret_cast<__half2*>(&g1hi);
                hA[j] = __hadd2(hA[j], __hfma2(fr2, __hsub2(a1, a0), a0));
                hB[j] = __hadd2(hB[j], __hfma2(fr2, __hsub2(b1, b0), b0));
            }
        }
        // flush run accumulators to fp32
#pragma unroll
        for (int j = 0; j < 4; j++) {
            float2 fa = __half22float2(hA[j]);
            float2 fb = __half22float2(hB[j]);
            acc[j][0] += fa.x;  acc[j][1] += fa.y;
            acc[j][2] += fb.x;  acc[j][3] += fb.y;
        }
    }

    // out[s, x, y]: y = 32*j + l, lane-consecutive -> coalesced 128B stores
    float* ob = out + (size_t)sl0 * 16384 + x * 128 + l;
#pragma unroll
    for (int s = 0; s < 4; s++)
#pragma unroll
        for (int j = 0; j < 4; j++)
            ob[s * 16384 + 32 * j] = acc[j][s];
}

// ----------------------------------------------------------------------------
extern "C" void kernel_launch(void* const* d_in, const int* in_sizes, int n_in,
                              void* d_out, int out_size) {
    (void)in_sizes; (void)n_in; (void)out_size;
    const float* feat = (const float*)d_in[0];
    float* out = (float*)d_out;

    int smem_bytes = 128 * QROW * 8;                 // 196608
    cudaFuncSetAttribute(k_bp, cudaFuncAttributeMaxDynamicSharedMemorySize,
                         smem_bytes);

    k_filter<<<2048, 256>>>(feat);
    k_bp<<<1024, 1024, smem_bytes>>>(out);
}

// round 10
// speedup vs baseline: 3.5517x; 1.1369x over previous
#include <cuda_runtime.h>
#include <cuda_fp16.h>

#define MPIF 3.14159265358979323846f

// ----------------------------------------------------------------------------
// FBP pipeline (2 kernels, SIMT — tcgen05 unavailable: harness lowers via
// compute_103 which rejects arch-specific PTX):
//   K1: filter — circular conv of the 16 BASE frames with the exact
//       closed-form ramp kernel (scaled by pi/128). (filter ∘ lerp = lerp ∘ filter)
//   K2: backproject — 4 slices per block packed as ONE 64-bit smem slot
//       (4 x fp16): one LDS.64 = one tap for all 4 slices. Lerp as two HFMA2
//       (om*g0 + fr*g1 into run accumulator); fp16 run-accumulation over 8
//       angles flushed to fp32. Lane = consecutive y -> conflict-free LDS;
//       floor folded into LDS address (fp32 magic).
// ----------------------------------------------------------------------------

__device__ float g_Fbase[16 * 1024 * 128];       // filtered base frames, 8 MB

// --------------------------- K1: filter -------------------------------------
__global__ __launch_bounds__(256) void k_filter(const float* __restrict__ feat) {
    __shared__ float hk[256];                    // hker duplicated: hk[i]=h[i&127]
    int tid = threadIdx.x;
    {
        int n = tid & 127;
        float h;
        if (n == 0) h = 0.25f;
        else if (n & 1) {
            float sv = sinpif((float)n * (1.0f / 128.0f));
            h = -1.0f / (16384.0f * sv * sv);
        } else h = 0.0f;
        hk[tid] = h * (MPIF / 128.0f);           // fold pi/A scale into filter
    }
    __syncthreads();

    int lane = tid & 31;
    int wid  = tid >> 5;
    int r = blockIdx.x * 8 + wid;                // row 0..16383 = t*1024 + s
    const float* row = feat + (size_t)r * 128;

    float rv[4];
    rv[0] = row[lane];      rv[1] = row[lane + 32];
    rv[2] = row[lane + 64]; rv[3] = row[lane + 96];
    float a0 = 0.f, a1 = 0.f, a2 = 0.f, a3 = 0.f;

#pragma unroll
    for (int kb = 0; kb < 4; kb++) {
        float rsel = rv[kb];
#pragma unroll
        for (int kk = 0; kk < 32; kk++) {
            float x = __shfl_sync(0xffffffffu, rsel, kk);
            int base = lane + 128 - (kb * 32 + kk);   // in [1,255]
            a0 += x * hk[base];
            a1 += x * hk[base + 32];
            a2 += x * hk[base + 64];
            a3 += x * hk[base + 96];
        }
    }
    float* o = g_Fbase + (size_t)r * 128;
    o[lane] = a0; o[lane + 32] = a1; o[lane + 64] = a2; o[lane + 96] = a3;
}

// ------------------------ K2: backprojection --------------------------------
// grid = 1024: block b -> quad = b>>2 (slices 4q..4q+3), part = b&3 (x band).
// smem: 128 angle rows x 192 slots, slot = 8B = 4 x fp16 (slices 0..3),
// 32-slot zero guards each side. 196608 B total.
static constexpr int QROW = 192;                     // slots per angle row
extern __shared__ __align__(16) unsigned long long s_q[];   // 128*192 slots

__global__ __launch_bounds__(1024, 1) void k_bp(float* __restrict__ out) {
    __shared__ float2 scs[128];                  // (cos, sin)

    int tid  = threadIdx.x;
    int quad = blockIdx.x >> 2;
    int part = blockIdx.x & 3;
    int sl0  = quad * 4;                         // first of 4 slices

    if (tid < 128) {
        float t = (float)tid * (1.0f / 128.0f);
        scs[tid] = make_float2(cospif(t), sinpif(t));
    }

    // zero guard slots: 128 rows x (32 left + 32 right)
    for (int g = tid; g < 8192; g += 1024) {
        int a = g >> 6;
        int q = g & 63;
        int col = (q < 32) ? q : (128 + q);      // [0,32) and [160,192)
        s_q[a * QROW + col] = 0ull;
    }

    // interior fill: thread -> (w, angle eighth z). 3 frames x 4 slices in regs,
    // emit 16 packed angle rows of one detector column.
    {
        int w = tid & 127;
        int z = tid >> 7;                        // 0..7 -> angles [16z,16z+16)
        float f[3][4], d[2][4];
#pragma unroll
        for (int k = 0; k < 3; k++) {
            int t = (2 * z + k) & 15;
#pragma unroll
            for (int s = 0; s < 4; s++)
                f[k][s] = g_Fbase[((size_t)t * 1024 + sl0 + s) * 128 + w];
        }
#pragma unroll
        for (int k = 0; k < 2; k++)
#pragma unroll
            for (int s = 0; s < 4; s++) d[k][s] = f[k + 1][s] - f[k][s];

#pragma unroll
        for (int aa = 0; aa < 16; aa++) {
            int a = z * 16 + aa;
            int k = aa >> 3;
            float v = (float)(aa & 7) * 0.125f;
            float v0 = fmaf(v, d[k][0], f[k][0]);
            float v1 = fmaf(v, d[k][1], f[k][1]);
            float v2 = fmaf(v, d[k][2], f[k][2]);
            float v3 = fmaf(v, d[k][3], f[k][3]);
            __half2 lo = __floats2half2_rn(v0, v1);
            __half2 hi = __floats2half2_rn(v2, v3);
            unsigned long long pk =
                (unsigned long long)(*reinterpret_cast<unsigned*>(&lo)) |
                ((unsigned long long)(*reinterpret_cast<unsigned*>(&hi)) << 32);
            s_q[a * QROW + 32 + w] = pk;
        }
    }
    __syncthreads();

    // main loop: warp -> x = part*32 + warpid, lane = y (consecutive).
    int w5 = tid >> 5;
    int l  = tid & 31;
    int x  = part * 32 + w5;
    float xa = (float)x - 63.5f;
    float la = (float)l;

    unsigned sb = (unsigned)__cvta_generic_to_shared(s_q);

    float acc[4][4];                             // [j][slice] fp32
#pragma unroll
    for (int j = 0; j < 4; j++)
#pragma unroll
        for (int s = 0; s < 4; s++) acc[j][s] = 0.f;

    const __half2 hz   = __float2half2_rn(0.f);
    const __half2 hone = __float2half2_rn(1.f);

    for (int run = 0; run < 16; run++) {
        __half2 hA[4], hB[4];                    // run accumulators: (s0,s1),(s2,s3)
#pragma unroll
        for (int j = 0; j < 4; j++) { hA[j] = hz; hB[j] = hz; }

#pragma unroll
        for (int aa = 0; aa < 8; aa++) {
            int a = run * 8 + aa;
            float2 cs = scs[a];
            float xc = fmaf(xa, cs.x, fmaf(la, cs.y, 95.5f)); // center+guard
            // magic row base: addr = rb + 8*float_as_int(u + 2^23-0.5)
            unsigned rb = sb + (unsigned)(a * (QROW * 8)) - 0x58000000u;
#pragma unroll
            for (int j = 0; j < 4; j++) {
                float u  = fmaf((float)(32 * j) - 63.5f, cs.y, xc);
                float t  = u + 8388607.5f;       // 2^23-0.5: RN -> floor
                float fl = t - 8388608.0f;       // floor(u), exact
                float fr = u - fl;               // frac, exact
                __half2 fr2 = __float2half2_rn(fr);
                __half2 om2 = __hsub2(hone, fr2);
                unsigned addr = rb + ((unsigned)__float_as_int(t) << 3);
                unsigned g0lo, g0hi, g1lo, g1hi;
                asm("ld.shared.v2.b32 {%0,%1}, [%2];"
                    : "=r"(g0lo), "=r"(g0hi) : "r"(addr));
                asm("ld.shared.v2.b32 {%0,%1}, [%2+8];"
                    : "=r"(g1lo), "=r"(g1hi) : "r"(addr));
                __half2 a0 = *reinterpret_cast<__half2*>(&g0lo);
                __half2 b0 = *reinterpret_cast<__half2*>(&g0hi);
                __half2 a1 = *reinterpret_cast<__half2*>(&g1lo);
                __half2 b1 = *reinterpret_cast<__half2*>(&g1hi);
                hA[j] = __hfma2(om2, a0, hA[j]);
                hA[j] = __hfma2(fr2, a1, hA[j]);
                hB[j] = __hfma2(om2, b0, hB[j]);
                hB[j] = __hfma2(fr2, b1, hB[j]);
            }
        }
        // flush run accumulators to fp32
#pragma unroll
        for (int j = 0; j < 4; j++) {
            float2 fa = __half22float2(hA[j]);
            float2 fb = __half22float2(hB[j]);
            acc[j][0] += fa.x;  acc[j][1] += fa.y;
            acc[j][2] += fb.x;  acc[j][3] += fb.y;
        }
    }

    // out[s, x, y]: y = 32*j + l, lane-consecutive -> coalesced 128B stores
    float* ob = out + (size_t)sl0 * 16384 + x * 128 + l;
#pragma unroll
    for (int s = 0; s < 4; s++)
#pragma unroll
        for (int j = 0; j < 4; j++)
            ob[s * 16384 + 32 * j] = acc[j][s];
}

// ----------------------------------------------------------------------------
extern "C" void kernel_launch(void* const* d_in, const int* in_sizes, int n_in,
                              void* d_out, int out_size) {
    (void)in_sizes; (void)n_in; (void)out_size;
    const float* feat = (const float*)d_in[0];
    float* out = (float*)d_out;

    int smem_bytes = 128 * QROW * 8;                 // 196608
    cudaFuncSetAttribute(k_bp, cudaFuncAttributeMaxDynamicSharedMemorySize,
                         smem_bytes);

    k_filter<<<2048, 256>>>(feat);
    k_bp<<<1024, 1024, smem_bytes>>>(out);
}

// round 12
// speedup vs baseline: 3.6094x; 1.0162x over previous
#include <cuda_runtime.h>
#include <cuda_fp16.h>

#define MPIF 3.14159265358979323846f

// ----------------------------------------------------------------------------
// FBP as banded GEMM on mma.sync (HMMA fallback; tcgen05 is 'a'-gated and the
// harness lowers via compute_103):
//   K1 k_filter : exact closed-form ramp conv of 16 base frames -> fp16 F
//   K2 k_wbuild : per (pixel-tile tau, K-chunk ch) 64-wide banded weight rows.
//       17 chunks: ch=0 frame0/angles 0-7 (i0 role), ch=1..15 frame ch with
//       its 16 contiguous angles, ch=16 frame0/angles 120-127 (i1 role).
//       Splitting the circular wrap keeps every chunk's detector span <= 53.
//   K3 k_gemm   : per (s-block, tile): D[128 s,128 p] = sum_ch A[s,64]·B^T,
//                 m16n8k16 mma.sync, fp32 accum, reg-prefetch pipeline.
// ----------------------------------------------------------------------------

static constexpr int NCH = 17;                   // K-chunks per tile

__device__ __half g_Fh[16 * 1024 * 128];         // filtered frames fp16, 4 MB
__device__ __half g_W16[128 * NCH * 128 * 64];   // weights [tau*17+ch][p][w], 34 MB
__device__ int    g_base[128 * NCH];             // band base col per (tau,ch)

// --------------------------- K1: filter -------------------------------------
__global__ __launch_bounds__(256) void k_filter(const float* __restrict__ feat) {
    __shared__ float hk[256];
    int tid = threadIdx.x;
    {
        int n = tid & 127;
        float h;
        if (n == 0) h = 0.25f;
        else if (n & 1) {
            float sv = sinpif((float)n * (1.0f / 128.0f));
            h = -1.0f / (16384.0f * sv * sv);
        } else h = 0.0f;
        hk[tid] = h * (MPIF / 128.0f);           // fold pi/A scale into filter
    }
    __syncthreads();

    int lane = tid & 31;
    int wid  = tid >> 5;
    int r = blockIdx.x * 8 + wid;                // row = t*1024 + s
    const float* row = feat + (size_t)r * 128;

    float rv[4];
    rv[0] = row[lane];      rv[1] = row[lane + 32];
    rv[2] = row[lane + 64]; rv[3] = row[lane + 96];
    float a0 = 0.f, a1 = 0.f, a2 = 0.f, a3 = 0.f;

#pragma unroll
    for (int kb = 0; kb < 4; kb++) {
        float rsel = rv[kb];
#pragma unroll
        for (int kk = 0; kk < 32; kk++) {
            float x = __shfl_sync(0xffffffffu, rsel, kk);
            int base = lane + 128 - (kb * 32 + kk);
            a0 += x * hk[base];
            a1 += x * hk[base + 32];
            a2 += x * hk[base + 64];
            a3 += x * hk[base + 96];
        }
    }
    __half* o = g_Fh + (size_t)r * 128;
    o[lane]      = __float2half_rn(a0);
    o[lane + 32] = __float2half_rn(a1);
    o[lane + 64] = __float2half_rn(a2);
    o[lane + 96] = __float2half_rn(a3);
}

// --------------------------- K2: weight build --------------------------------
// Tile = 8(x) x 16(y) pixels; pixel p = dx*16+dy.
// Chunk ch: angles a = 8*ch-8+i, i in [ilo,ihi) (no wrap by construction):
//   cf = i<8 ? i/8 (frame is i1 of a) : 1-(i-8)/8 (frame is i0 of a).
__global__ __launch_bounds__(128) void k_wbuild() {
    __shared__ float sw[128 * 65];
    __shared__ float red[128];
    int bid = blockIdx.x, tau = bid / NCH, ch = bid % NCH;
    int ilo = (ch == 0)  ? 8 : 0;
    int ihi = (ch == 16) ? 8 : 16;
    int p = threadIdx.x;
    int dx = p >> 4, dy = p & 15;
    float px = (float)((tau >> 3) * 8 + dx)  - 63.5f;
    float py = (float)((tau & 7) * 16 + dy) - 63.5f;

    float umin = 1e30f;
    for (int i = ilo; i < ihi; i++) {
        int a = 8 * ch - 8 + i;                  // in [0,128), no wrap
        float th = (float)a * (1.0f / 128.0f);
        float u = px * cospif(th) + py * sinpif(th) + 63.5f;
        umin = fminf(umin, u);
    }
    red[p] = umin; __syncthreads();
    for (int o = 64; o > 0; o >>= 1) {
        if (p < o) red[p] = fminf(red[p], red[p + o]);
        __syncthreads();
    }
    int base = (int)floorf(red[0]) - 2;
    base = max(0, min(64, base)) & ~7;

    float* w64 = sw + p * 65;
    for (int k = 0; k < 64; k++) w64[k] = 0.f;
    for (int i = ilo; i < ihi; i++) {
        int a = 8 * ch - 8 + i;
        float cf = (i < 8) ? (float)i * 0.125f : 1.0f - (float)(i - 8) * 0.125f;
        float th = (float)a * (1.0f / 128.0f);
        float u = px * cospif(th) + py * sinpif(th) + 63.5f;
        float fl = floorf(u);
        int i0 = (int)fl;
        float fr = u - fl;
        int k0 = i0 - base;
        if (i0 >= 0 && i0 < 128 && k0 >= 0 && k0 < 64)
            w64[k0] += cf * (1.0f - fr);
        int i1 = i0 + 1, k1 = k0 + 1;
        if (i1 >= 0 && i1 < 128 && k1 >= 0 && k1 < 64)
            w64[k1] += cf * fr;
    }
    __half* Wp = g_W16 + (size_t)bid * 8192 + (size_t)p * 64;
#pragma unroll
    for (int k = 0; k < 64; k++) Wp[k] = __float2half_rn(w64[k]);
    if (p == 0) g_base[bid] = base;
}

// --------------------------- K3: GEMM ----------------------------------------
// grid = 1024: bid -> tau = bid>>3 (pixel tile), s-block = bid&7 (128 slices).
// 256 thr, 8 warps: warp = (mw = w&3: 32 s) x (nw = w>>2: 64 p).
// Smem rows padded to 72 halves (144 B): frag LDS.32 banks distinct.
static constexpr int SAW = 72;

__global__ __launch_bounds__(256, 2) void k_gemm(float* __restrict__ out) {
    __shared__ __half As[128 * SAW];             // F block: row s, 64 band cols
    __shared__ __half Bs[128 * SAW];             // W: row p, 64 band cols

    int tid = threadIdx.x;
    int tau = blockIdx.x >> 3;
    int s0  = (blockIdx.x & 7) * 128;
    int l = tid & 31, w = tid >> 5;
    int mw = w & 3, nw = w >> 2;
    int g = l >> 2, t4 = l & 3;

    float c[2][8][4];
#pragma unroll
    for (int mt = 0; mt < 2; mt++)
#pragma unroll
        for (int nt = 0; nt < 8; nt++)
#pragma unroll
            for (int q = 0; q < 4; q++) c[mt][nt][q] = 0.f;

    uint4 pf[8];
    {   // prefetch chunk 0 (frame 0)
        int base = g_base[tau * NCH];
        const uint4* Ag = (const uint4*)(g_Fh + (size_t)s0 * 128 + base);
        const uint4* Bg = (const uint4*)(g_W16 + (size_t)(tau * NCH) * 8192);
#pragma unroll
        for (int k = 0; k < 8; k++) {
            int c8 = tid + 256 * k;
            int row = (c8 >> 3) & 127;
            int j = c8 & 7;
            pf[k] = (c8 < 1024) ? Ag[row * 16 + j] : Bg[row * 8 + j];
        }
    }

    for (int t = 0; t < NCH; t++) {
        // commit prefetched chunk to smem
#pragma unroll
        for (int k = 0; k < 8; k++) {
            int c8 = tid + 256 * k;
            int row = (c8 >> 3) & 127;
            int j = c8 & 7;
            __half* dst = (c8 < 1024) ? &As[row * SAW + j * 8]
                                      : &Bs[row * SAW + j * 8];
            *(uint4*)dst = pf[k];
        }
        __syncthreads();
        if (t < NCH - 1) {                       // prefetch next (hidden by mma)
            int f = (t + 1) & 15;                // chunk 16 -> frame 0
            int base = g_base[tau * NCH + t + 1];
            const uint4* Ag = (const uint4*)(g_Fh + ((size_t)f * 1024 + s0) * 128 + base);
            const uint4* Bg = (const uint4*)(g_W16 + (size_t)(tau * NCH + t + 1) * 8192);
#pragma unroll
            for (int k = 0; k < 8; k++) {
                int c8 = tid + 256 * k;
                int row = (c8 >> 3) & 127;
                int j = c8 & 7;
                pf[k] = (c8 < 1024) ? Ag[row * 16 + j] : Bg[row * 8 + j];
            }
        }
#pragma unroll
        for (int kk = 0; kk < 64; kk += 16) {
            unsigned a[2][4];
#pragma unroll
            for (int mt = 0; mt < 2; mt++) {
                const __half* ar = &As[(mw * 32 + mt * 16 + g) * SAW + kk + t4 * 2];
                a[mt][0] = *(const unsigned*)ar;
                a[mt][1] = *(const unsigned*)(ar + 8 * SAW);
                a[mt][2] = *(const unsigned*)(ar + 8);
                a[mt][3] = *(const unsigned*)(ar + 8 * SAW + 8);
            }
#pragma unroll
            for (int nt = 0; nt < 8; nt++) {
                const __half* br = &Bs[(nw * 64 + nt * 8 + g) * SAW + kk + t4 * 2];
                unsigned b0 = *(const unsigned*)br;
                unsigned b1 = *(const unsigned*)(br + 8);
#pragma unroll
                for (int mt = 0; mt < 2; mt++) {
                    asm volatile(
                        "mma.sync.aligned.m16n8k16.row.col.f32.f16.f16.f32 "
                        "{%0,%1,%2,%3}, {%4,%5,%6,%7}, {%8,%9}, {%0,%1,%2,%3};"
                        : "+f"(c[mt][nt][0]), "+f"(c[mt][nt][1]),
                          "+f"(c[mt][nt][2]), "+f"(c[mt][nt][3])
                        : "r"(a[mt][0]), "r"(a[mt][1]),
                          "r"(a[mt][2]), "r"(a[mt][3]),
                          "r"(b0), "r"(b1));
                }
            }
        }
        __syncthreads();
    }

    // epilogue: D row = slice, cols = 2 consecutive y -> float2 stores
    int x0 = (tau >> 3) * 8, y0 = (tau & 7) * 16;
#pragma unroll
    for (int mt = 0; mt < 2; mt++) {
        int srow = s0 + mw * 32 + mt * 16 + g;
#pragma unroll
        for (int nt = 0; nt < 8; nt++) {
            int p = nw * 64 + nt * 8 + t4 * 2;
            int dx = p >> 4, dy = p & 15;
            size_t off = (size_t)srow * 16384 + (size_t)(x0 + dx) * 128 + (y0 + dy);
            *(float2*)(out + off) = make_float2(c[mt][nt][0], c[mt][nt][1]);
            *(float2*)(out + off + (size_t)8 * 16384) =
                make_float2(c[mt][nt][2], c[mt][nt][3]);
        }
    }
}

// ----------------------------------------------------------------------------
extern "C" void kernel_launch(void* const* d_in, const int* in_sizes, int n_in,
                              void* d_out, int out_size) {
    (void)in_sizes; (void)n_in; (void)out_size;
    const float* feat = (const float*)d_in[0];
    float* out = (float*)d_out;

    k_filter<<<2048, 256>>>(feat);
    k_wbuild<<<128 * NCH, 128>>>();
    k_gemm<<<1024, 256>>>(out);
}

// round 13
// speedup vs baseline: 3.6940x; 1.0234x over previous
#include <cuda_runtime.h>
#include <cuda_fp16.h>

#define MPIF 3.14159265358979323846f

// ----------------------------------------------------------------------------
// FBP as banded GEMM on mma.sync (HMMA fallback; tcgen05 is 'a'-gated and the
// harness lowers via compute_103):
//   K1 k_filter : exact closed-form ramp conv of 16 base frames -> fp16 F
//   K2 k_wbuild : per (pixel-tile tau, K-chunk ch) 64-wide banded weight rows.
//       17 chunks (circular wrap split: ch=0 frame0/angles 0-7, ch=1..15
//       frame ch contiguous, ch=16 frame0/angles 120-127) -> span <= 53 each.
//   K3 k_gemm   : per (s-block, tile): D[128 s,128 p] = sum_ch A[s,64]·B^T,
//       m16n8k16 mma.sync, fp32 accum. cp.async double-buffered smem pipeline
//       (no register prefetch -> no spills at the 128-reg / 2-CTA point).
// ----------------------------------------------------------------------------

static constexpr int NCH = 17;                   // K-chunks per tile

__device__ __half g_Fh[16 * 1024 * 128];         // filtered frames fp16, 4 MB
__device__ __half g_W16[128 * NCH * 128 * 64];   // weights [tau*17+ch][p][w], 34 MB
__device__ int    g_base[128 * NCH];             // band base col per (tau,ch)

// --------------------------- K1: filter -------------------------------------
__global__ __launch_bounds__(256) void k_filter(const float* __restrict__ feat) {
    __shared__ float hk[256];
    int tid = threadIdx.x;
    {
        int n = tid & 127;
        float h;
        if (n == 0) h = 0.25f;
        else if (n & 1) {
            float sv = sinpif((float)n * (1.0f / 128.0f));
            h = -1.0f / (16384.0f * sv * sv);
        } else h = 0.0f;
        hk[tid] = h * (MPIF / 128.0f);           // fold pi/A scale into filter
    }
    __syncthreads();

    int lane = tid & 31;
    int wid  = tid >> 5;
    int r = blockIdx.x * 8 + wid;                // row = t*1024 + s
    const float* row = feat + (size_t)r * 128;

    float rv[4];
    rv[0] = row[lane];      rv[1] = row[lane + 32];
    rv[2] = row[lane + 64]; rv[3] = row[lane + 96];
    float a0 = 0.f, a1 = 0.f, a2 = 0.f, a3 = 0.f;

#pragma unroll
    for (int kb = 0; kb < 4; kb++) {
        float rsel = rv[kb];
#pragma unroll
        for (int kk = 0; kk < 32; kk++) {
            float x = __shfl_sync(0xffffffffu, rsel, kk);
            int base = lane + 128 - (kb * 32 + kk);
            a0 += x * hk[base];
            a1 += x * hk[base + 32];
            a2 += x * hk[base + 64];
            a3 += x * hk[base + 96];
        }
    }
    __half* o = g_Fh + (size_t)r * 128;
    o[lane]      = __float2half_rn(a0);
    o[lane + 32] = __float2half_rn(a1);
    o[lane + 64] = __float2half_rn(a2);
    o[lane + 96] = __float2half_rn(a3);
}

// --------------------------- K2: weight build --------------------------------
__global__ __launch_bounds__(128) void k_wbuild() {
    __shared__ float sw[128 * 65];
    __shared__ float red[128];
    int bid = blockIdx.x, tau = bid / NCH, ch = bid % NCH;
    int ilo = (ch == 0)  ? 8 : 0;
    int ihi = (ch == 16) ? 8 : 16;
    int p = threadIdx.x;
    int dx = p >> 4, dy = p & 15;
    float px = (float)((tau >> 3) * 8 + dx)  - 63.5f;
    float py = (float)((tau & 7) * 16 + dy) - 63.5f;

    float umin = 1e30f;
    for (int i = ilo; i < ihi; i++) {
        int a = 8 * ch - 8 + i;                  // in [0,128), no wrap
        float th = (float)a * (1.0f / 128.0f);
        float u = px * cospif(th) + py * sinpif(th) + 63.5f;
        umin = fminf(umin, u);
    }
    red[p] = umin; __syncthreads();
    for (int o = 64; o > 0; o >>= 1) {
        if (p < o) red[p] = fminf(red[p], red[p + o]);
        __syncthreads();
    }
    int base = (int)floorf(red[0]) - 2;
    base = max(0, min(64, base)) & ~7;

    float* w64 = sw + p * 65;
    for (int k = 0; k < 64; k++) w64[k] = 0.f;
    for (int i = ilo; i < ihi; i++) {
        int a = 8 * ch - 8 + i;
        float cf = (i < 8) ? (float)i * 0.125f : 1.0f - (float)(i - 8) * 0.125f;
        float th = (float)a * (1.0f / 128.0f);
        float u = px * cospif(th) + py * sinpif(th) + 63.5f;
        float fl = floorf(u);
        int i0 = (int)fl;
        float fr = u - fl;
        int k0 = i0 - base;
        if (i0 >= 0 && i0 < 128 && k0 >= 0 && k0 < 64)
            w64[k0] += cf * (1.0f - fr);
        int i1 = i0 + 1, k1 = k0 + 1;
        if (i1 >= 0 && i1 < 128 && k1 >= 0 && k1 < 64)
            w64[k1] += cf * fr;
    }
    __half* Wp = g_W16 + (size_t)bid * 8192 + (size_t)p * 64;
#pragma unroll
    for (int k = 0; k < 64; k++) Wp[k] = __float2half_rn(w64[k]);
    if (p == 0) g_base[bid] = base;
}

// --------------------------- K3: GEMM ----------------------------------------
// grid = 1024: bid -> tau = bid>>3 (pixel tile), s-block = bid&7 (128 slices).
// 256 thr, 8 warps: warp = (mw = w&3: 32 s) x (nw = w>>2: 64 p).
// Smem rows padded to 72 halves (144 B = 9 x 16B): frag LDS banks distinct,
// cp.async 16B dst alignment holds.
static constexpr int SAW = 72;
static constexpr int STG = 2 * 128 * SAW;        // halves per stage (A+B)

extern __shared__ __half sm_g[];

__global__ __launch_bounds__(256, 2) void k_gemm(float* __restrict__ out) {
    int tid = threadIdx.x;
    int tau = blockIdx.x >> 3;
    int s0  = (blockIdx.x & 7) * 128;
    int l = tid & 31, w = tid >> 5;
    int mw = w & 3, nw = w >> 2;
    int g = l >> 2, t4 = l & 3;

    float c[2][8][4];
#pragma unroll
    for (int mt = 0; mt < 2; mt++)
#pragma unroll
        for (int nt = 0; nt < 8; nt++)
#pragma unroll
            for (int q = 0; q < 4; q++) c[mt][nt][q] = 0.f;

    // --- async chunk loader: A(F band) + B(W) -> stage buffer --------------
    auto issue_chunk = [&](int t, int stage) {
        int f = t & 15;                          // chunk 16 -> frame 0
        int base = g_base[tau * NCH + t];
        const uint4* Ag = (const uint4*)(g_Fh + ((size_t)f * 1024 + s0) * 128 + base);
        const uint4* Bg = (const uint4*)(g_W16 + (size_t)(tau * NCH + t) * 8192);
        __half* As = sm_g + stage * STG;
        __half* Bs = As + 128 * SAW;
#pragma unroll
        for (int k = 0; k < 8; k++) {
            int c8 = tid + 256 * k;
            int row = (c8 >> 3) & 127;
            int j = c8 & 7;
            const uint4* src = (c8 < 1024) ? &Ag[row * 16 + j] : &Bg[row * 8 + j];
            __half* dst = ((c8 < 1024) ? As : Bs) + row * SAW + j * 8;
            unsigned da = (unsigned)__cvta_generic_to_shared(dst);
            asm volatile("cp.async.cg.shared.global [%0], [%1], 16;"
                         :: "r"(da), "l"(src) : "memory");
        }
        asm volatile("cp.async.commit_group;" ::: "memory");
    };

    issue_chunk(0, 0);

    for (int t = 0; t < NCH; t++) {
        if (t + 1 < NCH) {
            issue_chunk(t + 1, (t + 1) & 1);
            asm volatile("cp.async.wait_group 1;" ::: "memory");
        } else {
            asm volatile("cp.async.wait_group 0;" ::: "memory");
        }
        __syncthreads();

        const __half* As = sm_g + (t & 1) * STG;
        const __half* Bs = As + 128 * SAW;
#pragma unroll
        for (int kk = 0; kk < 64; kk += 16) {
            unsigned a[2][4];
#pragma unroll
            for (int mt = 0; mt < 2; mt++) {
                const __half* ar = &As[(mw * 32 + mt * 16 + g) * SAW + kk + t4 * 2];
                a[mt][0] = *(const unsigned*)ar;
                a[mt][1] = *(const unsigned*)(ar + 8 * SAW);
                a[mt][2] = *(const unsigned*)(ar + 8);
                a[mt][3] = *(const unsigned*)(ar + 8 * SAW + 8);
            }
#pragma unroll
            for (int nt = 0; nt < 8; nt++) {
                const __half* br = &Bs[(nw * 64 + nt * 8 + g) * SAW + kk + t4 * 2];
                unsigned b0 = *(const unsigned*)br;
                unsigned b1 = *(const unsigned*)(br + 8);
#pragma unroll
                for (int mt = 0; mt < 2; mt++) {
                    asm volatile(
                        "mma.sync.aligned.m16n8k16.row.col.f32.f16.f16.f32 "
                        "{%0,%1,%2,%3}, {%4,%5,%6,%7}, {%8,%9}, {%0,%1,%2,%3};"
                        : "+f"(c[mt][nt][0]), "+f"(c[mt][nt][1]),
                          "+f"(c[mt][nt][2]), "+f"(c[mt][nt][3])
                        : "r"(a[mt][0]), "r"(a[mt][1]),
                          "r"(a[mt][2]), "r"(a[mt][3]),
                          "r"(b0), "r"(b1));
                }
            }
        }
        __syncthreads();
    }

    // epilogue: D row = slice, cols = 2 consecutive y -> float2 stores
    int x0 = (tau >> 3) * 8, y0 = (tau & 7) * 16;
#pragma unroll
    for (int mt = 0; mt < 2; mt++) {
        int srow = s0 + mw * 32 + mt * 16 + g;
#pragma unroll
        for (int nt = 0; nt < 8; nt++) {
            int p = nw * 64 + nt * 8 + t4 * 2;
            int dx = p >> 4, dy = p & 15;
            size_t off = (size_t)srow * 16384 + (size_t)(x0 + dx) * 128 + (y0 + dy);
            *(float2*)(out + off) = make_float2(c[mt][nt][0], c[mt][nt][1]);
            *(float2*)(out + off + (size_t)8 * 16384) =
                make_float2(c[mt][nt][2], c[mt][nt][3]);
        }
    }
}

// ----------------------------------------------------------------------------
extern "C" void kernel_launch(void* const* d_in, const int* in_sizes, int n_in,
                              void* d_out, int out_size) {
    (void)in_sizes; (void)n_in; (void)out_size;
    const float* feat = (const float*)d_in[0];
    float* out = (float*)d_out;

    int smem_bytes = 2 * STG * (int)sizeof(__half);      // 73728
    cudaFuncSetAttribute(k_gemm, cudaFuncAttributeMaxDynamicSharedMemorySize,
                         smem_bytes);

    k_filter<<<2048, 256>>>(feat);
    k_wbuild<<<128 * NCH, 128>>>();
    k_gemm<<<1024, 256, smem_bytes>>>(out);
}